// round 4
// baseline (speedup 1.0000x reference)
#include <cuda_runtime.h>
#include <cstdint>

#define SEQ 4096
#define HD 64
#define NBATCH 4
#define TQ 64
#define TN 64
#define NIT (SEQ / TN)
#define PAD 68
#define NTH 256
#define CEXP 0.18033688011112042f  // log2(e) / temperature(8)

// smem float offsets (tiles are 64 x PAD)
#define O_QP 0
#define O_K0 4352
#define O_K1 8704
#define O_V0 13056
#define O_V1 17408
#define O_RS 21760  // 64 rowsums
#define SMEM_BYTES (21824 * 4)

__device__ __forceinline__ uint32_t f2tf(float x) {
    uint32_t u;
    asm("cvt.rna.tf32.f32 %0, %1;" : "=r"(u) : "f"(x));
    return u;
}

__device__ __forceinline__ void mma8(float c[4], const uint32_t a[4], const uint32_t b[2]) {
    asm volatile(
        "mma.sync.aligned.m16n8k8.row.col.f32.tf32.tf32.f32 "
        "{%0,%1,%2,%3}, {%4,%5,%6,%7}, {%8,%9}, {%0,%1,%2,%3};\n"
        : "+f"(c[0]), "+f"(c[1]), "+f"(c[2]), "+f"(c[3])
        : "r"(a[0]), "r"(a[1]), "r"(a[2]), "r"(a[3]), "r"(b[0]), "r"(b[1]));
}

__global__ void __launch_bounds__(NTH, 2)
attn_fused(const float* __restrict__ Q, const float* __restrict__ K,
           const float* __restrict__ V, float* __restrict__ outp,
           float* __restrict__ attnp) {
    extern __shared__ float sm[];
    const int tid = threadIdx.x, w = tid >> 5, lane = tid & 31;
    const int g = lane >> 2, tg = lane & 3;
    const int b = blockIdx.x >> 6;
    const int q0 = (blockIdx.x & 63) << 6;   // 64-row q tile
    const int wq = (w >> 1) * 16, wn = (w & 1) * 32;

    const float* Qb = Q + ((size_t)b * SEQ + q0) * HD;
    const float* Kb = K + (size_t)b * SEQ * HD;
    const float* Vb = V + (size_t)b * SEQ * HD;

    float* QP = sm + O_QP;
    float* RS = sm + O_RS;
    float* KsA[2] = {sm + O_K0, sm + O_K1};
    float* VsA[2] = {sm + O_V0, sm + O_V1};

    if (tid < TQ) RS[tid] = 0.f;

    // ---- stage Q tile (64x64, tf32-rounded, PAD layout) ----
#pragma unroll
    for (int t = 0; t < 4; ++t) {
        int idx = tid + t * NTH;
        int r = idx >> 4, c4 = (idx & 15) << 2;
        float4 v = *reinterpret_cast<const float4*>(Qb + r * HD + c4);
        *reinterpret_cast<uint4*>(QP + r * PAD + c4) =
            make_uint4(f2tf(v.x), f2tf(v.y), f2tf(v.z), f2tf(v.w));
    }
    __syncthreads();

    // ---- hoist Q fragments (loop-invariant, 16-row warp tile) ----
    uint32_t qf[8][4];
#pragma unroll
    for (int kk = 0; kk < 8; ++kk) {
        const int k0 = kk * 8;
        const int r = wq + g;
        qf[kk][0] = __float_as_uint(QP[r * PAD + k0 + tg]);
        qf[kk][1] = __float_as_uint(QP[(r + 8) * PAD + k0 + tg]);
        qf[kk][2] = __float_as_uint(QP[r * PAD + k0 + tg + 4]);
        qf[kk][3] = __float_as_uint(QP[(r + 8) * PAD + k0 + tg + 4]);
    }

    float4 kr[4], vr[4];
    auto ldg64 = [&](const float* src, int n0, float4 rr[4]) {
#pragma unroll
        for (int t = 0; t < 4; ++t) {
            int idx = tid + t * NTH;
            int r = idx >> 4, c4 = (idx & 15) << 2;
            rr[t] = *reinterpret_cast<const float4*>(src + (size_t)(n0 + r) * HD + c4);
        }
    };
    auto sts64 = [&](float* dst, const float4 rr[4]) {
#pragma unroll
        for (int t = 0; t < 4; ++t) {
            int idx = tid + t * NTH;
            int r = idx >> 4, c4 = (idx & 15) << 2;
            *reinterpret_cast<uint4*>(dst + r * PAD + c4) =
                make_uint4(f2tf(rr[t].x), f2tf(rr[t].y), f2tf(rr[t].z), f2tf(rr[t].w));
        }
    };

    // ================= Phase A: rowsums of exp =================
    ldg64(Kb, 0, kr);
    sts64(KsA[0], kr);
    __syncthreads();
    ldg64(Kb, TN, kr);

    float rsum[2] = {0.f, 0.f};
    for (int it = 0; it < NIT; ++it) {
        const int s = it & 1;
        const float* Ks = KsA[s];
        float c[4][4] = {};
#pragma unroll
        for (int kk = 0; kk < 8; ++kk) {
            const int k0 = kk * 8;
#pragma unroll
            for (int j = 0; j < 4; ++j) {
                const int n = wn + j * 8 + g;
                uint32_t bb[2] = {__float_as_uint(Ks[n * PAD + k0 + tg]),
                                  __float_as_uint(Ks[n * PAD + k0 + tg + 4])};
                mma8(c[j], qf[kk], bb);
            }
        }
#pragma unroll
        for (int j = 0; j < 4; ++j) {
            rsum[0] += exp2f(c[j][0] * CEXP) + exp2f(c[j][1] * CEXP);
            rsum[1] += exp2f(c[j][2] * CEXP) + exp2f(c[j][3] * CEXP);
        }
        if (it + 1 < NIT) sts64(KsA[s ^ 1], kr);
        if (it + 2 < NIT) ldg64(Kb, (it + 2) * TN, kr);
        __syncthreads();
    }
#pragma unroll
    for (int h = 0; h < 2; ++h) {
        float v = rsum[h];
        v += __shfl_xor_sync(0xffffffffu, v, 1);
        v += __shfl_xor_sync(0xffffffffu, v, 2);
        if (tg == 0) atomicAdd(&RS[wq + h * 8 + g], v);
    }
    __syncthreads();
    float lr[2];  // -log2(rowsum): folded into the exp2 argument
#pragma unroll
    for (int h = 0; h < 2; ++h) lr[h] = -log2f(RS[wq + h * 8 + g]);
    __syncthreads();

    // ================= Phase B: attn + AV =================
    float o[4][4] = {};
    ldg64(Kb, 0, kr);
    ldg64(Vb, 0, vr);
    sts64(KsA[0], kr);
    sts64(VsA[0], vr);
    __syncthreads();
    ldg64(Kb, TN, kr);
    ldg64(Vb, TN, vr);

    for (int it = 0; it < NIT; ++it) {
        const int s = it & 1;
        const int n0 = it * TN;
        const float* Ks = KsA[s];
        float c[4][4] = {};
#pragma unroll
        for (int kk = 0; kk < 8; ++kk) {
            const int k0 = kk * 8;
#pragma unroll
            for (int j = 0; j < 4; ++j) {
                const int n = wn + j * 8 + g;
                uint32_t bb[2] = {__float_as_uint(Ks[n * PAD + k0 + tg]),
                                  __float_as_uint(Ks[n * PAD + k0 + tg + 4])};
                mma8(c[j], qf[kk], bb);
            }
        }

        // normalized probabilities (in-place) + attn store
        {
            const int row = q0 + wq + g;
            float* ar = attnp + ((size_t)b * SEQ + row) * SEQ + n0 + wn;
#pragma unroll
            for (int j = 0; j < 4; ++j) {
                c[j][0] = exp2f(fmaf(c[j][0], CEXP, lr[0]));
                c[j][1] = exp2f(fmaf(c[j][1], CEXP, lr[0]));
                c[j][2] = exp2f(fmaf(c[j][2], CEXP, lr[1]));
                c[j][3] = exp2f(fmaf(c[j][3], CEXP, lr[1]));
                *reinterpret_cast<float2*>(ar + j * 8 + 2 * tg) =
                    make_float2(c[j][0], c[j][1]);
                *reinterpret_cast<float2*>(ar + (size_t)8 * SEQ + j * 8 + 2 * tg) =
                    make_float2(c[j][2], c[j][3]);
            }
        }

        __syncthreads();  // all warps done AV(it-1): P buffer reusable

        // store tf32 P into QP
        {
            const int r = wq + g;
#pragma unroll
            for (int j = 0; j < 4; ++j) {
                const int col = wn + j * 8 + 2 * tg;
                *reinterpret_cast<uint2*>(&QP[r * PAD + col]) =
                    make_uint2(f2tf(c[j][0]), f2tf(c[j][1]));
                *reinterpret_cast<uint2*>(&QP[(r + 8) * PAD + col]) =
                    make_uint2(f2tf(c[j][2]), f2tf(c[j][3]));
            }
        }
        if (it + 1 < NIT) {
            sts64(KsA[s ^ 1], kr);
            sts64(VsA[s ^ 1], vr);
        }
        if (it + 2 < NIT) {
            ldg64(Kb, (it + 2) * TN, kr);
            ldg64(Vb, (it + 2) * TN, vr);
        }
        __syncthreads();  // P + next K/V staged

        // AV: O += P @ V
        const float* Vs = VsA[s];
#pragma unroll
        for (int kk = 0; kk < 8; ++kk) {
            const int k0 = kk * 8;
            uint32_t a[4];
            const int r = wq + g;
            a[0] = __float_as_uint(QP[r * PAD + k0 + tg]);
            a[1] = __float_as_uint(QP[(r + 8) * PAD + k0 + tg]);
            a[2] = __float_as_uint(QP[r * PAD + k0 + tg + 4]);
            a[3] = __float_as_uint(QP[(r + 8) * PAD + k0 + tg + 4]);
#pragma unroll
            for (int j = 0; j < 4; ++j) {
                uint32_t bb[2] = {
                    __float_as_uint(Vs[(k0 + tg) * PAD + wn + j * 8 + g]),
                    __float_as_uint(Vs[(k0 + tg + 4) * PAD + wn + j * 8 + g])};
                mma8(o[j], a, bb);
            }
        }
    }

    // ---- epilogue: write out [B,S,64] ----
    {
        const int row = q0 + wq + g;
        float* orow = outp + ((size_t)b * SEQ + row) * HD;
#pragma unroll
        for (int j = 0; j < 4; ++j) {
            const int col = wn + j * 8 + 2 * tg;
            *reinterpret_cast<float2*>(orow + col) = make_float2(o[j][0], o[j][1]);
            *reinterpret_cast<float2*>(orow + 8 * HD + col) =
                make_float2(o[j][2], o[j][3]);
        }
    }
}

extern "C" void kernel_launch(void* const* d_in, const int* in_sizes, int n_in,
                              void* d_out, int out_size) {
    const float* q = (const float*)d_in[0];
    const float* k = (const float*)d_in[1];
    const float* v = (const float*)d_in[2];
    float* outp = (float*)d_out;
    float* attnp = outp + (size_t)NBATCH * SEQ * HD;

    cudaFuncSetAttribute(attn_fused, cudaFuncAttributeMaxDynamicSharedMemorySize,
                         SMEM_BYTES);
    attn_fused<<<NBATCH * 64, NTH, SMEM_BYTES>>>(q, k, v, outp, attnp);
}

// round 5
// speedup vs baseline: 1.4731x; 1.4731x over previous
#include <cuda_runtime.h>
#include <cstdint>

#define SEQ 4096
#define HD 64
#define NBATCH 4
#define TQ 128
#define TN 64
#define NIT 64
#define PAD 68
#define NTH 256
#define CEXP 0.18033688011112042f  // log2(e)/temperature(8)

// smem float offsets
#define O_QP 0                 // Q (prologue) then P (phase B): 128*68 = 8704
#define O_K 8704               // 4 ring buffers of 64*68 = 4352
#define O_V (8704 + 17408)     // 4 ring buffers of 4352
#define O_RS (8704 + 17408 + 17408)
#define SMEM_BYTES ((O_RS + 128) * 4)

__device__ __forceinline__ uint32_t f2tf(float x) {
    uint32_t u;
    asm("cvt.rna.tf32.f32 %0, %1;" : "=r"(u) : "f"(x));
    return u;
}

__device__ __forceinline__ void mma8(float c[4], const uint32_t a[4], const uint32_t b[2]) {
    asm volatile(
        "mma.sync.aligned.m16n8k8.row.col.f32.tf32.tf32.f32 "
        "{%0,%1,%2,%3}, {%4,%5,%6,%7}, {%8,%9}, {%0,%1,%2,%3};\n"
        : "+f"(c[0]), "+f"(c[1]), "+f"(c[2]), "+f"(c[3])
        : "r"(a[0]), "r"(a[1]), "r"(a[2]), "r"(a[3]), "r"(b[0]), "r"(b[1]));
}

__global__ void __launch_bounds__(NTH, 1)
attn_fused(const float* __restrict__ Q, const float* __restrict__ K,
           const float* __restrict__ V, float* __restrict__ outp,
           float* __restrict__ attnp) {
    extern __shared__ float sm[];
    const int tid = threadIdx.x, w = tid >> 5, lane = tid & 31;
    const int g = lane >> 2, tg = lane & 3;
    const int b = blockIdx.x >> 5;
    const int q0 = (blockIdx.x & 31) << 7;  // 128-row q tile
    const int wq = (w >> 1) * 32, wn = (w & 1) * 32;

    const float* Qb = Q + ((size_t)b * SEQ + q0) * HD;
    const float* Kb = K + (size_t)b * SEQ * HD;
    const float* Vb = V + (size_t)b * SEQ * HD;

    float* QP = sm + O_QP;
    float* RS = sm + O_RS;

    if (tid < TQ) RS[tid] = 0.f;

    // ---- stage Q tile (128x64, tf32-rounded, PAD layout) ----
#pragma unroll
    for (int t = 0; t < 8; ++t) {
        int idx = tid + t * NTH;
        int r = idx >> 4, c4 = (idx & 15) << 2;
        float4 v = *reinterpret_cast<const float4*>(Qb + r * HD + c4);
        *reinterpret_cast<uint4*>(QP + r * PAD + c4) =
            make_uint4(f2tf(v.x), f2tf(v.y), f2tf(v.z), f2tf(v.w));
    }
    __syncthreads();

    // ---- hoist Q fragments (loop-invariant) ----
    uint32_t qf[8][2][4];
#pragma unroll
    for (int kk = 0; kk < 8; ++kk) {
        const int k0 = kk * 8;
#pragma unroll
        for (int i = 0; i < 2; ++i) {
            const int r = wq + i * 16 + g;
            qf[kk][i][0] = __float_as_uint(QP[r * PAD + k0 + tg]);
            qf[kk][i][1] = __float_as_uint(QP[(r + 8) * PAD + k0 + tg]);
            qf[kk][i][2] = __float_as_uint(QP[r * PAD + k0 + tg + 4]);
            qf[kk][i][3] = __float_as_uint(QP[(r + 8) * PAD + k0 + tg + 4]);
        }
    }

    float4 kr[4], vr[4];
    auto ldg64 = [&](const float* src, int n0, float4 rr[4]) {
#pragma unroll
        for (int t = 0; t < 4; ++t) {
            int idx = tid + t * NTH;
            int r = idx >> 4, c4 = (idx & 15) << 2;
            rr[t] = *reinterpret_cast<const float4*>(src + (size_t)(n0 + r) * HD + c4);
        }
    };
    auto sts64 = [&](float* dst, const float4 rr[4]) {
#pragma unroll
        for (int t = 0; t < 4; ++t) {
            int idx = tid + t * NTH;
            int r = idx >> 4, c4 = (idx & 15) << 2;
            *reinterpret_cast<uint4*>(dst + r * PAD + c4) =
                make_uint4(f2tf(rr[t].x), f2tf(rr[t].y), f2tf(rr[t].z), f2tf(rr[t].w));
        }
    };
    auto qk_issue = [&](float (&c)[2][4][4], const float* Ks) {
#pragma unroll
        for (int kk = 0; kk < 8; ++kk) {
            const int k0 = kk * 8;
#pragma unroll
            for (int j = 0; j < 4; ++j) {
                const int n = wn + j * 8 + g;
                uint32_t bb[2] = {__float_as_uint(Ks[n * PAD + k0 + tg]),
                                  __float_as_uint(Ks[n * PAD + k0 + tg + 4])};
                mma8(c[0][j], qf[kk][0], bb);
                mma8(c[1][j], qf[kk][1], bb);
            }
        }
    };

    // ================= Phase A: rowsums of exp (pipelined) =================
    float rsum[2][2] = {{0.f, 0.f}, {0.f, 0.f}};
    float cA[2][4][4] = {}, cB[2][4][4] = {};
    {
        ldg64(Kb, 0, kr);
        sts64(sm + O_K + 0 * 4352, kr);
        __syncthreads();
        ldg64(Kb, TN, kr);
        sts64(sm + O_K + 1 * 4352, kr);
        ldg64(Kb, 2 * TN, kr);
        __syncthreads();
        qk_issue(cA, sm + O_K + 0 * 4352);

        auto bodyA = [&](int it, float (&cc)[2][4][4], float (&cn)[2][4][4]) {
            if (it + 1 < NIT) {
#pragma unroll
                for (int i = 0; i < 2; ++i)
#pragma unroll
                    for (int j = 0; j < 4; ++j)
#pragma unroll
                        for (int t = 0; t < 4; ++t) cn[i][j][t] = 0.f;
                qk_issue(cn, sm + O_K + ((it + 1) & 3) * 4352);
            }
            if (it + 2 < NIT) sts64(sm + O_K + ((it + 2) & 3) * 4352, kr);
            if (it + 3 < NIT) ldg64(Kb, (it + 3) * TN, kr);
#pragma unroll
            for (int i = 0; i < 2; ++i)
#pragma unroll
                for (int j = 0; j < 4; ++j) {
                    rsum[i][0] += exp2f(cc[i][j][0] * CEXP) + exp2f(cc[i][j][1] * CEXP);
                    rsum[i][1] += exp2f(cc[i][j][2] * CEXP) + exp2f(cc[i][j][3] * CEXP);
                }
            __syncthreads();
        };
        for (int it = 0; it < NIT; it += 2) {
            bodyA(it, cA, cB);
            bodyA(it + 1, cB, cA);
        }
    }
#pragma unroll
    for (int i = 0; i < 2; ++i)
#pragma unroll
        for (int h = 0; h < 2; ++h) {
            float v = rsum[i][h];
            v += __shfl_xor_sync(0xffffffffu, v, 1);
            v += __shfl_xor_sync(0xffffffffu, v, 2);
            if (tg == 0) atomicAdd(&RS[wq + i * 16 + h * 8 + g], v);
        }
    __syncthreads();
    float lr[2][2];  // -log2(rowsum), folded into exp2
#pragma unroll
    for (int i = 0; i < 2; ++i)
#pragma unroll
        for (int h = 0; h < 2; ++h) lr[i][h] = -log2f(RS[wq + i * 16 + h * 8 + g]);
    __syncthreads();

    // ================= Phase B: attn + AV (pipelined) =================
    float o[2][4][4] = {};
    {
        ldg64(Kb, 0, kr);
        ldg64(Vb, 0, vr);
        sts64(sm + O_K + 0 * 4352, kr);
        sts64(sm + O_V + 0 * 4352, vr);
        __syncthreads();
        ldg64(Kb, TN, kr);
        ldg64(Vb, TN, vr);
        sts64(sm + O_K + 1 * 4352, kr);
        sts64(sm + O_V + 1 * 4352, vr);
        ldg64(Kb, 2 * TN, kr);
        ldg64(Vb, 2 * TN, vr);
        __syncthreads();
#pragma unroll
        for (int i = 0; i < 2; ++i)
#pragma unroll
            for (int j = 0; j < 4; ++j)
#pragma unroll
                for (int t = 0; t < 4; ++t) cA[i][j][t] = 0.f;
        qk_issue(cA, sm + O_K + 0 * 4352);

        auto bodyB = [&](int it, float (&cc)[2][4][4], float (&cn)[2][4][4]) {
            if (it + 1 < NIT) {
#pragma unroll
                for (int i = 0; i < 2; ++i)
#pragma unroll
                    for (int j = 0; j < 4; ++j)
#pragma unroll
                        for (int t = 0; t < 4; ++t) cn[i][j][t] = 0.f;
                qk_issue(cn, sm + O_K + ((it + 1) & 3) * 4352);
            }
            const int n0 = it * TN;
            // exp (normalized, in place) + attn streaming store
#pragma unroll
            for (int i = 0; i < 2; ++i) {
                const int row = q0 + wq + i * 16 + g;
                float* ar = attnp + ((size_t)b * SEQ + row) * SEQ + n0 + wn;
#pragma unroll
                for (int j = 0; j < 4; ++j) {
                    cc[i][j][0] = exp2f(fmaf(cc[i][j][0], CEXP, lr[i][0]));
                    cc[i][j][1] = exp2f(fmaf(cc[i][j][1], CEXP, lr[i][0]));
                    cc[i][j][2] = exp2f(fmaf(cc[i][j][2], CEXP, lr[i][1]));
                    cc[i][j][3] = exp2f(fmaf(cc[i][j][3], CEXP, lr[i][1]));
                    __stcs(reinterpret_cast<float2*>(ar + j * 8 + 2 * tg),
                           make_float2(cc[i][j][0], cc[i][j][1]));
                    __stcs(reinterpret_cast<float2*>(ar + (size_t)8 * SEQ + j * 8 + 2 * tg),
                           make_float2(cc[i][j][2], cc[i][j][3]));
                }
            }
            __syncthreads();  // AV(it-1) finished reading P
            // P tile (tf32) into QP
#pragma unroll
            for (int i = 0; i < 2; ++i) {
                const int r = wq + i * 16 + g;
#pragma unroll
                for (int j = 0; j < 4; ++j) {
                    const int col = wn + j * 8 + 2 * tg;
                    *reinterpret_cast<uint2*>(&QP[r * PAD + col]) =
                        make_uint2(f2tf(cc[i][j][0]), f2tf(cc[i][j][1]));
                    *reinterpret_cast<uint2*>(&QP[(r + 8) * PAD + col]) =
                        make_uint2(f2tf(cc[i][j][2]), f2tf(cc[i][j][3]));
                }
            }
            if (it + 2 < NIT) {
                sts64(sm + O_K + ((it + 2) & 3) * 4352, kr);
                sts64(sm + O_V + ((it + 2) & 3) * 4352, vr);
            }
            if (it + 3 < NIT) {
                ldg64(Kb, (it + 3) * TN, kr);
                ldg64(Vb, (it + 3) * TN, vr);
            }
            __syncthreads();  // P + staged tiles visible
            // AV: O += P @ V
            const float* Vs = sm + O_V + (it & 3) * 4352;
#pragma unroll
            for (int kk = 0; kk < 8; ++kk) {
                const int k0 = kk * 8;
                uint32_t a[2][4];
#pragma unroll
                for (int i = 0; i < 2; ++i) {
                    const int r = wq + i * 16 + g;
                    a[i][0] = __float_as_uint(QP[r * PAD + k0 + tg]);
                    a[i][1] = __float_as_uint(QP[(r + 8) * PAD + k0 + tg]);
                    a[i][2] = __float_as_uint(QP[r * PAD + k0 + tg + 4]);
                    a[i][3] = __float_as_uint(QP[(r + 8) * PAD + k0 + tg + 4]);
                }
#pragma unroll
                for (int j = 0; j < 4; ++j) {
                    uint32_t bb[2] = {
                        __float_as_uint(Vs[(k0 + tg) * PAD + wn + j * 8 + g]),
                        __float_as_uint(Vs[(k0 + tg + 4) * PAD + wn + j * 8 + g])};
                    mma8(o[0][j], a[0], bb);
                    mma8(o[1][j], a[1], bb);
                }
            }
        };
        for (int it = 0; it < NIT; it += 2) {
            bodyB(it, cA, cB);
            bodyB(it + 1, cB, cA);
        }
    }

    // ---- epilogue: write out [B,S,64] ----
#pragma unroll
    for (int i = 0; i < 2; ++i) {
        const int row = q0 + wq + i * 16 + g;
        float* orow = outp + ((size_t)b * SEQ + row) * HD;
#pragma unroll
        for (int j = 0; j < 4; ++j) {
            const int col = wn + j * 8 + 2 * tg;
            *reinterpret_cast<float2*>(orow + col) = make_float2(o[i][j][0], o[i][j][1]);
            *reinterpret_cast<float2*>(orow + 8 * HD + col) =
                make_float2(o[i][j][2], o[i][j][3]);
        }
    }
}

extern "C" void kernel_launch(void* const* d_in, const int* in_sizes, int n_in,
                              void* d_out, int out_size) {
    const float* q = (const float*)d_in[0];
    const float* k = (const float*)d_in[1];
    const float* v = (const float*)d_in[2];
    float* outp = (float*)d_out;
    float* attnp = outp + (size_t)NBATCH * SEQ * HD;

    cudaFuncSetAttribute(attn_fused, cudaFuncAttributeMaxDynamicSharedMemorySize,
                         SMEM_BYTES);
    attn_fused<<<NBATCH * 32, NTH, SMEM_BYTES>>>(q, k, v, outp, attnp);
}